// round 14
// baseline (speedup 1.0000x reference)
#include <cuda_runtime.h>
#include <math.h>
#include <mma.h>

using namespace nvcuda;

// ---------------------------------------------------------------------------
// DepthFormer (Nystrom attention) — round 14: direct fragment-store epilogue
// for simple GEMMs + warp-per-row softmax.  Base: R13 (9042us).
// seq = 32768, dim = 192, 4 layers.
// ---------------------------------------------------------------------------

#define DIM 192
#define SEQ 32768
#define FD 32          // depth (f)
#define NSP 1024       // spatial positions per depth slice (n)
#define ML 256         // spatial landmarks
#define SCALE_QK 0.07216878364870322f   // 192^-0.5

// ------------------------------ scratch ------------------------------------
__device__ float g_x  [SEQ * DIM];
__device__ float g_src[SEQ * DIM];
__device__ float g_qkv[SEQ * 3 * DIM];
__device__ float g_ql [32 * ML * DIM];
__device__ float g_kl [32 * ML * DIM];
__device__ float g_a1 [32 * NSP * ML];
__device__ float g_a2 [32 * ML * ML];
__device__ float g_a3 [32 * ML * NSP];
__device__ float g_zb [32 * ML * ML];
__device__ float g_z2 [32 * ML * ML];
__device__ float g_t1 [32 * ML * ML];
__device__ float g_t2 [32 * ML * ML];
__device__ float g_t3 [32 * ML * ML];
__device__ float g_a3v[32 * ML * DIM];
__device__ float g_zv [32 * ML * DIM];
__device__ float g_o  [SEQ * DIM];
__device__ float g_gg [SEQ * 4 * DIM];
__device__ float g_w1p[DIM * 8 * DIM];
__device__ float g_b1p[8 * DIM];
__device__ float g_rs [SEQ];
__device__ float g_red[2];

// ------------------------------ GEMM ---------------------------------------
struct GemmP {
    const float* A; const float* B; float* C; float* C2;
    const float* bias; const float* resid; const float* rowS;
    int K, diagMode, geglu;
    long lda, ldb, ldc, sA, sB, sC;
    float alpha, diag1, diag2;
};

#define CP16(dst_u32, src) \
    asm volatile("cp.async.cg.shared.global [%0], [%1], 16;" :: "r"(dst_u32), "l"(src))
#define CP_COMMIT() asm volatile("cp.async.commit_group;")

template<int N> __device__ __forceinline__ void cp_wait() {
    asm volatile("cp.async.wait_group %0;" :: "n"(N));
}

#define STG_OF(BM, BN) ((BM) * 36 + ((32 * ((BN) + 4) > (BN) * 36) ? 32 * ((BN) + 4) : (BN) * 36))
#define SMEM_BYTES(BM, BN, NST) ((NST) * STG_OF(BM, BN) * 4)

// TF32 wmma GEMM, cp.async NST-stage pipeline, 1 barrier per K-iter.
// M % BM == 0, N % BN == 0, K % 32 == 0, K >= 32*(NST-1), rows 16B aligned.
template<int TRANSB, int BM, int BN, int NTHR, int NST>
__global__ void __launch_bounds__(NTHR) tgemm(GemmP p) {
    constexpr int BK = 32;
    constexpr int LDA = 36;
    constexpr int LDBN = BN + 4;
    constexpr int LDBT = 36;
    constexpr int LDC = BN + 4;
    constexpr int STG = STG_OF(BM, BN);
    constexpr int NCA = BM * 8 / NTHR;
    constexpr int NCB = BN * 8 / NTHR;
    constexpr int WNB = BN / 32;
    extern __shared__ float smem[];

    int bz = blockIdx.z;
    const float* A = p.A + (long)bz * p.sA;
    const float* B = p.B + (long)bz * p.sB;
    float*       C = p.C + (long)bz * p.sC;
    int m0 = blockIdx.y * BM, n0 = blockIdx.x * BN;
    int tid = threadIdx.x;
    int warp = tid >> 5;
    int wm = (warp / WNB) * 32;
    int wn = (warp % WNB) * 32;

    const float* aG[NCA]; int aS[NCA];
    #pragma unroll
    for (int i = 0; i < NCA; i++) {
        int idx = tid + i * NTHR;
        aG[i] = A + (long)(m0 + (idx >> 3)) * p.lda + ((idx & 7) << 2);
        aS[i] = (idx >> 3) * LDA + ((idx & 7) << 2);
    }
    const float* bG[NCB]; int bS[NCB];
    if (!TRANSB) {
        #pragma unroll
        for (int i = 0; i < NCB; i++) {
            int idx = tid + i * NTHR;
            bG[i] = B + (long)(idx / (BN / 4)) * p.ldb + n0 + ((idx % (BN / 4)) << 2);
            bS[i] = BM * LDA + (idx / (BN / 4)) * LDBN + ((idx % (BN / 4)) << 2);
        }
    } else {
        #pragma unroll
        for (int i = 0; i < NCB; i++) {
            int idx = tid + i * NTHR;
            bG[i] = B + (long)(n0 + (idx >> 3)) * p.ldb + ((idx & 7) << 2);
            bS[i] = BM * LDA + (idx >> 3) * LDBT + ((idx & 7) << 2);
        }
    }
    unsigned smem_u32 = (unsigned)__cvta_generic_to_shared(smem);
    long bstep = TRANSB ? 32 : 32 * p.ldb;

    wmma::fragment<wmma::accumulator, 16, 16, 8, float> cfr[2][2];
    #pragma unroll
    for (int i = 0; i < 2; i++)
        #pragma unroll
        for (int j = 0; j < 2; j++) wmma::fill_fragment(cfr[i][j], 0.f);

    int NSTEP = p.K >> 5;
    #pragma unroll
    for (int s = 0; s < NST - 1; s++) {
        unsigned base = smem_u32 + s * (STG * 4);
        #pragma unroll
        for (int i = 0; i < NCA; i++) CP16(base + aS[i] * 4, aG[i] + s * 32);
        #pragma unroll
        for (int i = 0; i < NCB; i++) CP16(base + bS[i] * 4, bG[i] + s * bstep);
        CP_COMMIT();
    }

    int cbuf = 0;
    int pbuf = NST - 1;
    for (int s = 0; s < NSTEP; s++) {
        cp_wait<NST - 2>();
        __syncthreads();
        int pf = s + NST - 1;
        if (pf < NSTEP) {
            unsigned base = smem_u32 + pbuf * (STG * 4);
            #pragma unroll
            for (int i = 0; i < NCA; i++) CP16(base + aS[i] * 4, aG[i] + (long)pf * 32);
            #pragma unroll
            for (int i = 0; i < NCB; i++) CP16(base + bS[i] * 4, bG[i] + (long)pf * bstep);
        }
        CP_COMMIT();

        float* As = smem + cbuf * STG;
        float* Bs = As + BM * LDA;
        #pragma unroll
        for (int kk = 0; kk < BK; kk += 8) {
            wmma::fragment<wmma::matrix_a, 16, 16, 8, wmma::precision::tf32, wmma::row_major> a[2];
            #pragma unroll
            for (int i = 0; i < 2; i++)
                wmma::load_matrix_sync(a[i], &As[(wm + i * 16) * LDA + kk], LDA);
            if (!TRANSB) {
                wmma::fragment<wmma::matrix_b, 16, 16, 8, wmma::precision::tf32, wmma::row_major> b[2];
                #pragma unroll
                for (int j = 0; j < 2; j++)
                    wmma::load_matrix_sync(b[j], &Bs[kk * LDBN + wn + j * 16], LDBN);
                #pragma unroll
                for (int i = 0; i < 2; i++)
                    #pragma unroll
                    for (int j = 0; j < 2; j++)
                        wmma::mma_sync(cfr[i][j], a[i], b[j], cfr[i][j]);
            } else {
                wmma::fragment<wmma::matrix_b, 16, 16, 8, wmma::precision::tf32, wmma::col_major> b[2];
                #pragma unroll
                for (int j = 0; j < 2; j++)
                    wmma::load_matrix_sync(b[j], &Bs[(wn + j * 16) * LDBT + kk], LDBT);
                #pragma unroll
                for (int i = 0; i < 2; i++)
                    #pragma unroll
                    for (int j = 0; j < 2; j++)
                        wmma::mma_sync(cfr[i][j], a[i], b[j], cfr[i][j]);
            }
        }
        cbuf = (cbuf + 1 == NST) ? 0 : cbuf + 1;
        pbuf = (pbuf + 1 == NST) ? 0 : pbuf + 1;
    }
    cp_wait<0>();

    // ---- fast path: direct fragment store (no smem, no barriers) ----
    // usable when no elementwise row/col data needed and this tile does not
    // touch the diagonal of a diag-style output (diagMode or C2).
    {
        bool needDiag = (p.diagMode || p.C2) &&
                        (n0 < m0 + BM) && (m0 < n0 + BN);
        if (!p.geglu && !p.bias && !p.resid && !p.rowS && !needDiag) {
            float s1 = p.diagMode ? -p.alpha : p.alpha;
            #pragma unroll
            for (int i = 0; i < 2; i++)
                #pragma unroll
                for (int j = 0; j < 2; j++) {
                    #pragma unroll
                    for (int e = 0; e < cfr[i][j].num_elements; e++)
                        cfr[i][j].x[e] *= s1;
                    wmma::store_matrix_sync(
                        C + (long)(m0 + wm + i * 16) * p.ldc + n0 + wn + j * 16,
                        cfr[i][j], p.ldc, wmma::mem_row_major);
                }
            if (p.C2) {   // off-diagonal tile of C2 = diag2*I - v  ->  -v
                float* C2p = p.C2 + (long)bz * p.sC;
                #pragma unroll
                for (int i = 0; i < 2; i++)
                    #pragma unroll
                    for (int j = 0; j < 2; j++) {
                        #pragma unroll
                        for (int e = 0; e < cfr[i][j].num_elements; e++)
                            cfr[i][j].x[e] = -cfr[i][j].x[e];
                        wmma::store_matrix_sync(
                            C2p + (long)(m0 + wm + i * 16) * p.ldc + n0 + wn + j * 16,
                            cfr[i][j], p.ldc, wmma::mem_row_major);
                    }
            }
            return;
        }
    }

    // ---- general path: stage through smem ----
    __syncthreads();
    float* Cs = smem;
    #pragma unroll
    for (int i = 0; i < 2; i++)
        #pragma unroll
        for (int j = 0; j < 2; j++)
            wmma::store_matrix_sync(&Cs[(wm + i * 16) * LDC + wn + j * 16],
                                    cfr[i][j], LDC, wmma::mem_row_major);
    __syncthreads();

    if (p.geglu) {
        for (int i = tid; i < BM * (BN / 2); i += NTHR) {
            int r = i / (BN / 2), q = i % (BN / 2);
            int m = m0 + r;
            float sc = p.alpha * (p.rowS ? p.rowS[m] : 1.f);
            float av = Cs[r * LDC + 2 * q]     * sc + p.bias[n0 + 2 * q];
            float gv = Cs[r * LDC + 2 * q + 1] * sc + p.bias[n0 + 2 * q + 1];
            float ge = 0.5f * gv * (1.f + erff(gv * 0.70710678118654752f));
            C[(long)m * p.ldc + (n0 >> 1) + q] = av * ge;
        }
        return;
    }

    for (int i = tid; i < BM * BN; i += NTHR) {
        int r = i / BN, cn = i % BN;
        int m = m0 + r, n = n0 + cn;
        float v = Cs[r * LDC + cn] * p.alpha;
        if (p.rowS) v *= p.rowS[m];
        long co = (long)m * p.ldc + n;
        float out;
        if (p.diagMode) {
            out = (m == n ? p.diag1 : 0.f) - v;
        } else {
            out = v;
            if (p.bias)  out += p.bias[n];
            if (p.resid) out += p.resid[(long)bz * p.sC + co];
        }
        C[co] = out;
        if (p.C2) p.C2[(long)bz * p.sC + co] = (m == n ? p.diag2 : 0.f) - v;
    }
}

static void gemm_full(const float* A, const float* B, float* C, float* C2,
                      const float* bias, const float* resid, const float* rowS,
                      int M, int N, int K,
                      long lda, long ldb, long ldc,
                      long sA, long sB, long sC,
                      int batch, float alpha, int transB,
                      int diagMode, float diag1, float diag2, int geglu) {
    GemmP p{A, B, C, C2, bias, resid, rowS, K, diagMode, geglu,
            lda, ldb, ldc, sA, sB, sC, alpha, diag1, diag2};
    if (M <= 256) {
        dim3 grid(N / 64, M / 64, batch);
        if (transB) tgemm<1, 64, 64, 128, 3><<<grid, 128, SMEM_BYTES(64, 64, 3)>>>(p);
        else        tgemm<0, 64, 64, 128, 3><<<grid, 128, SMEM_BYTES(64, 64, 3)>>>(p);
    } else {
        dim3 grid(N / 64, M / 128, batch);
        if (transB) tgemm<1, 128, 64, 256, 4><<<grid, 256, SMEM_BYTES(128, 64, 4)>>>(p);
        else        tgemm<0, 128, 64, 256, 4><<<grid, 256, SMEM_BYTES(128, 64, 4)>>>(p);
    }
}

static void gemm(const float* A, const float* B, float* C,
                 const float* bias, const float* resid, const float* rowS,
                 int M, int N, int K,
                 long lda, long ldb, long ldc,
                 long sA, long sB, long sC,
                 int batch, float alpha, int transB) {
    gemm_full(A, B, C, 0, bias, resid, rowS, M, N, K, lda, ldb, ldc, sA, sB, sC,
              batch, alpha, transB, 0, 0.f, 0.f, 0);
}

// --------------------------- elementwise / reductions -----------------------
__device__ __forceinline__ float warp_red_sum(float v) {
    #pragma unroll
    for (int o = 16; o > 0; o >>= 1) v += __shfl_xor_sync(0xffffffffu, v, o);
    return v;
}
__device__ __forceinline__ float warp_red_max(float v) {
    #pragma unroll
    for (int o = 16; o > 0; o >>= 1) v = fmaxf(v, __shfl_xor_sync(0xffffffffu, v, o));
    return v;
}

__global__ void rownorm_k(const float* __restrict__ x, float* __restrict__ s,
                          const float* __restrict__ g, int gidx, int rows) {
    int warp = (blockIdx.x * blockDim.x + threadIdx.x) >> 5;
    int lane = threadIdx.x & 31;
    if (warp >= rows) return;
    const float* xr = x + (long)warp * DIM;
    float acc = 0.f;
    #pragma unroll
    for (int i = 0; i < 6; i++) { float v = xr[lane + i * 32]; acc += v * v; }
    acc = warp_red_sum(acc);
    if (lane == 0) s[warp] = g[gidx] / fmaxf(sqrtf(acc), 1e-5f);
}

__global__ void scale_norm_k(const float* __restrict__ x, float* __restrict__ y,
                             const float* __restrict__ g, int gidx, int rows) {
    int warp = (blockIdx.x * blockDim.x + threadIdx.x) >> 5;
    int lane = threadIdx.x & 31;
    if (warp >= rows) return;
    const float* xr = x + (long)warp * DIM;
    float v[6], s = 0.f;
    #pragma unroll
    for (int i = 0; i < 6; i++) { v[i] = xr[lane + i * 32]; s += v[i] * v[i]; }
    s = warp_red_sum(s);
    float scale = g[gidx] / fmaxf(sqrtf(s), 1e-5f);
    float* yr = y + (long)warp * DIM;
    #pragma unroll
    for (int i = 0; i < 6; i++) yr[lane + i * 32] = v[i] * scale;
}

// warp-per-row softmax; EL = elements per lane (len = 32*EL); 8 rows/block.
template<int EL>
__global__ void __launch_bounds__(256) softmax_warp_k(float* __restrict__ x, long rows) {
    long row = (long)blockIdx.x * 8 + (threadIdx.x >> 5);
    if (row >= rows) return;
    int lane = threadIdx.x & 31;
    float* xr = x + row * (32 * EL);
    float v[EL];
    float mx = -3.0e38f;
    #pragma unroll
    for (int i = 0; i < EL; i++) { v[i] = xr[lane + (i << 5)]; mx = fmaxf(mx, v[i]); }
    mx = warp_red_max(mx);
    float s = 0.f;
    #pragma unroll
    for (int i = 0; i < EL; i++) { v[i] = expf(v[i] - mx); s += v[i]; }
    s = warp_red_sum(s);
    float inv = 1.f / s;
    #pragma unroll
    for (int i = 0; i < EL; i++) xr[lane + (i << 5)] = v[i] * inv;
}

__global__ void landmark_k(const float* __restrict__ qkv,
                           float* __restrict__ ql, float* __restrict__ kl) {
    int idx = blockIdx.x * blockDim.x + threadIdx.x;
    if (idx >= 32 * ML * DIM) return;
    int d = idx % DIM;
    int j = (idx / DIM) % ML;
    int b = idx / (DIM * ML);
    long base = ((long)b * NSP + j * 4) * (3 * DIM);
    float q = 0.f, k = 0.f;
    #pragma unroll
    for (int i = 0; i < 4; i++) {
        q += qkv[base + (long)i * (3 * DIM) + d];
        k += qkv[base + (long)i * (3 * DIM) + DIM + d];
    }
    ql[idx] = q * 0.25f;
    kl[idx] = k * 0.25f;
}

// red[0] = 1 (softmax rows sum to 1); red[1] cleared for colsum max
__global__ void reset2_k(float* r) {
    if (threadIdx.x == 0) r[0] = 1.0f;
    if (threadIdx.x == 1) r[1] = 0.f;
}

__global__ void colsum_max_k(const float* __restrict__ x, int m, float* red) {
    long col = blockIdx.x;
    int b = (int)(col / m), j = (int)(col % m);
    const float* xb = x + (long)b * m * m;
    __shared__ float sh[32];
    int tid = threadIdx.x, lane = tid & 31, w = tid >> 5, nw = blockDim.x >> 5;
    float s = 0.f;
    for (int i = tid; i < m; i += blockDim.x) s += fabsf(xb[(long)i * m + j]);
    s = warp_red_sum(s);
    if (lane == 0) sh[w] = s;
    __syncthreads();
    if (tid == 0) {
        float t = 0.f;
        for (int i = 0; i < nw; i++) t += sh[i];
        atomicMax((int*)(red + 1), __float_as_int(t));
    }
}

__global__ void zinit_k(const float* __restrict__ x, float* __restrict__ z,
                        const float* __restrict__ red, int m, long total) {
    long idx = (long)blockIdx.x * blockDim.x + threadIdx.x;
    if (idx >= total) return;
    long mm = (long)m * m;
    long b = idx / mm;
    int ij = (int)(idx % mm);
    int r = ij / m, c = ij % m;
    float inv = 1.f / (red[0] * red[1]);
    z[idx] = x[b * mm + (long)c * m + r] * inv;
}

__global__ void permw1_k(const float* __restrict__ w1, const float* __restrict__ b1,
                         float* __restrict__ w1p, float* __restrict__ b1p) {
    int idx = blockIdx.x * blockDim.x + threadIdx.x;
    if (idx < 8 * DIM) {
        int j = idx >> 1;
        b1p[idx] = (idx & 1) ? b1[j + 4 * DIM] : b1[j];
    }
    if (idx >= DIM * 8 * DIM) return;
    int n = idx % (8 * DIM), k = idx / (8 * DIM);
    int j = n >> 1;
    int src = (n & 1) ? j + 4 * DIM : j;
    w1p[idx] = w1[k * (8 * DIM) + src];
}

__global__ void patchify_k(const float* __restrict__ vol, float* __restrict__ out) {
    long idx = (long)blockIdx.x * blockDim.x + threadIdx.x;
    if (idx >= (long)SEQ * DIM) return;
    int j = (int)(idx % DIM);
    long t = idx / DIM;
    int d = (int)(t / NSP);
    int rem = (int)(t % NSP);
    int h = rem / 32, w = rem % 32;
    int p1 = j / 24;
    int p2 = (j / 3) & 7;
    int c = j % 3;
    long off = ((long)c * 32 + d) * 65536 + (long)(h * 8 + p1) * 256 + (w * 8 + p2);
    out[idx] = vol[off];
}

// --------------------- fused depth attention (f=32 per spatial pos) ---------
__global__ void __launch_bounds__(256) depth_scores_k(
        const float* __restrict__ qkv, float* __restrict__ a2out,
        float* __restrict__ red) {
    extern __shared__ float sm[];
    float* q = sm;
    float* k = sm + 32 * 196;
    float* S = k + 32 * 196;
    int nb = blockIdx.x, t = threadIdx.x;

    for (int idx = t; idx < 32 * DIM; idx += 256) {
        int f = idx / DIM, d = idx % DIM;
        long base = ((long)f * NSP + nb) * (3 * DIM);
        q[f * 196 + d] = qkv[base + d];
        k[f * 196 + d] = qkv[base + DIM + d];
    }
    __syncthreads();

    int i = t >> 3, j0 = t & 7;
    float s[4];
    #pragma unroll
    for (int jj = 0; jj < 4; jj++) {
        int j = j0 + 8 * jj;
        float acc = 0.f;
        for (int d = 0; d < DIM; d++) acc += q[i * 196 + d] * k[j * 196 + d];
        s[jj] = acc * SCALE_QK;
    }
    float mx = fmaxf(fmaxf(s[0], s[1]), fmaxf(s[2], s[3]));
    #pragma unroll
    for (int o = 4; o > 0; o >>= 1) mx = fmaxf(mx, __shfl_xor_sync(0xffffffffu, mx, o));
    float sum = 0.f;
    #pragma unroll
    for (int jj = 0; jj < 4; jj++) { s[jj] = expf(s[jj] - mx); sum += s[jj]; }
    #pragma unroll
    for (int o = 4; o > 0; o >>= 1) sum += __shfl_xor_sync(0xffffffffu, sum, o);
    float inv = 1.f / sum;
    #pragma unroll
    for (int jj = 0; jj < 4; jj++) {
        int j = j0 + 8 * jj;
        float v = s[jj] * inv;
        S[i * 33 + j] = v;
        a2out[(long)nb * 1024 + i * 32 + j] = v;
    }
    __syncthreads();
    if (t < 32) {               // column sums only (rowsum == 1 by softmax)
        float cs = 0.f;
        for (int r = 0; r < 32; r++) cs += S[r * 33 + t];
        cs = warp_red_max(cs);
        if (t == 0) atomicMax((int*)(red + 1), __float_as_int(cs));
    }
}

__device__ __forceinline__ void mm32(const float* A, const float* B, float* C,
                                     int t, int diag, float cst) {
    int i = t >> 3, j0 = t & 7;
    float acc[4] = {0.f, 0.f, 0.f, 0.f};
    #pragma unroll
    for (int kk = 0; kk < 32; kk++) {
        float a = A[i * 33 + kk];
        #pragma unroll
        for (int jj = 0; jj < 4; jj++) acc[jj] += a * B[kk * 33 + j0 + 8 * jj];
    }
    #pragma unroll
    for (int jj = 0; jj < 4; jj++) {
        int j = j0 + 8 * jj;
        C[i * 33 + j] = diag ? ((i == j ? cst : 0.f) - acc[jj]) : cst * acc[jj];
    }
}
__device__ __forceinline__ void mm32dual(const float* A, const float* B,
                                         float* C1, float* C2, int t, float cst) {
    int i = t >> 3, j0 = t & 7;
    float acc[4] = {0.f, 0.f, 0.f, 0.f};
    #pragma unroll
    for (int kk = 0; kk < 32; kk++) {
        float a = A[i * 33 + kk];
        #pragma unroll
        for (int jj = 0; jj < 4; jj++) acc[jj] += a * B[kk * 33 + j0 + 8 * jj];
    }
    #pragma unroll
    for (int jj = 0; jj < 4; jj++) {
        int j = j0 + 8 * jj;
        C1[i * 33 + j] = acc[jj];
        C2[i * 33 + j] = (i == j ? cst : 0.f) - acc[jj];
    }
}

__global__ void __launch_bounds__(256) depth_pinv_o_k(
        const float* __restrict__ a2in, const float* __restrict__ qkv,
        const float* __restrict__ red, float* __restrict__ Oout) {
    extern __shared__ float sm[];
    float* A  = sm;
    float* Z0 = A  + 1056;
    float* Z1 = Z0 + 1056;
    float* T1 = Z1 + 1056;
    float* T2 = T1 + 1056;
    float* T3 = T2 + 1056;
    float* V  = T3 + 1056;
    int nb = blockIdx.x, t = threadIdx.x;

    for (int idx = t; idx < 1024; idx += 256)
        A[(idx >> 5) * 33 + (idx & 31)] = a2in[(long)nb * 1024 + idx];
    for (int idx = t; idx < 32 * DIM; idx += 256) {
        int f = idx / DIM, d = idx % DIM;
        V[f * DIM + d] = qkv[((long)f * NSP + nb) * (3 * DIM) + 2 * DIM + d];
    }
    float inv = 1.f / (red[0] * red[1]);
    __syncthreads();
    for (int idx = t; idx < 1024; idx += 256) {
        int r = idx >> 5, c = idx & 31;
        Z0[r * 33 + c] = A[c * 33 + r] * inv;
    }
    __syncthreads();

    float* P = Z0; float* Pn = Z1;
    #pragma unroll 1
    for (int it = 0; it < 6; it++) {
        mm32dual(A, P, T1, T2, t, 7.f);   __syncthreads();
        mm32(T1, T2, T3, t, 1, 15.f);     __syncthreads();
        mm32(T1, T3, T2, t, 1, 13.f);     __syncthreads();
        mm32(P,  T2, Pn, t, 0, 0.25f);    __syncthreads();
        float* tmp = P; P = Pn; Pn = tmp;
    }
    mm32(A, P, T1, t, 0, 1.f);  __syncthreads();
    mm32(T1, A, T2, t, 0, 1.f); __syncthreads();

    int i = t >> 3, d0 = t & 7;
    #pragma unroll 4
    for (int m = 0; m < 24; m++) {
        int d = d0 + 8 * m;
        float acc = 0.f;
        #pragma unroll
        for (int kk = 0; kk < 32; kk++) acc += T2[i * 33 + kk] * V[kk * DIM + d];
        Oout[((long)i * NSP + nb) * DIM + d] = acc;
    }
}

// ------------------------------ pinv (spatial, m=256) -----------------------
static void run_pinv(float* X, int m, int batch,
                     float* Z, float* Z2, float* T1, float* T2, float* T3,
                     float* red) {
    long mm = (long)m * m;
    long total = mm * batch;
    reset2_k<<<1, 32>>>(red);
    colsum_max_k<<<batch * m, 128>>>(X, m, red);
    zinit_k<<<(int)((total + 255) / 256), 256>>>(X, Z, red, m, total);
    float* zc = Z; float* zn = Z2;
    for (int it = 0; it < 6; it++) {
        gemm_full(X, zc, T1, T2, 0, 0, 0, m, m, m, m, m, m, mm, mm, mm,
                  batch, 1.f, 0, 0, 0.f, 7.f, 0);
        gemm_full(T1, T2, T3, 0, 0, 0, 0, m, m, m, m, m, m, mm, mm, mm,
                  batch, 1.f, 0, 1, 15.f, 0.f, 0);
        gemm_full(T1, T3, T2, 0, 0, 0, 0, m, m, m, m, m, m, mm, mm, mm,
                  batch, 1.f, 0, 1, 13.f, 0.f, 0);
        gemm(zc, T2, zn, 0, 0, 0, m, m, m, m, m, m, mm, mm, mm, batch, 0.25f, 0);
        float* tmp = zc; zc = zn; zn = tmp;
    }
}

// ------------------------------ launch -------------------------------------
template <typename T>
static float* symptr(T& sym) { void* p = 0; cudaGetSymbolAddress(&p, sym); return (float*)p; }

extern "C" void kernel_launch(void* const* d_in, const int* in_sizes, int n_in,
                              void* d_out, int out_size) {
    const float* volume      = (const float*)d_in[0];
    const float* patch_w     = (const float*)d_in[1];
    const float* patch_b     = (const float*)d_in[2];
    const float* pos_emb     = (const float*)d_in[3];
    const float* gd          = (const float*)d_in[4];
    const float* qkv_depth   = (const float*)d_in[5];
    const float* outw_depth  = (const float*)d_in[6];
    const float* outb_depth  = (const float*)d_in[7];
    const float* gs          = (const float*)d_in[8];
    const float* qkv_spatial = (const float*)d_in[9];
    const float* outw_spatial= (const float*)d_in[10];
    const float* outb_spatial= (const float*)d_in[11];
    const float* gf          = (const float*)d_in[12];
    const float* ff_w1       = (const float*)d_in[13];
    const float* ff_b1       = (const float*)d_in[14];
    const float* ff_w2       = (const float*)d_in[15];
    const float* ff_b2       = (const float*)d_in[16];
    const float* g_fin       = (const float*)d_in[17];

    float* X   = symptr(g_x);
    float* SRC = symptr(g_src);
    float* QKV = symptr(g_qkv);
    float* QL  = symptr(g_ql);
    float* KL  = symptr(g_kl);
    float* A1  = symptr(g_a1);
    float* A2  = symptr(g_a2);
    float* A3  = symptr(g_a3);
    float* Z   = symptr(g_zb);
    float* Z2  = symptr(g_z2);
    float* T1  = symptr(g_t1);
    float* T2  = symptr(g_t2);
    float* T3  = symptr(g_t3);
    float* A3V = symptr(g_a3v);
    float* ZV  = symptr(g_zv);
    float* O   = symptr(g_o);
    float* GG  = symptr(g_gg);
    float* W1P = symptr(g_w1p);
    float* B1P = symptr(g_b1p);
    float* RS  = symptr(g_rs);
    float* RED = symptr(g_red);

    cudaFuncSetAttribute((void*)tgemm<0, 128, 64, 256, 4>,
        cudaFuncAttributeMaxDynamicSharedMemorySize, SMEM_BYTES(128, 64, 4));
    cudaFuncSetAttribute((void*)tgemm<1, 128, 64, 256, 4>,
        cudaFuncAttributeMaxDynamicSharedMemorySize, SMEM_BYTES(128, 64, 4));
    cudaFuncSetAttribute((void*)tgemm<0, 64, 64, 128, 3>,
        cudaFuncAttributeMaxDynamicSharedMemorySize, SMEM_BYTES(64, 64, 3));
    cudaFuncSetAttribute((void*)tgemm<1, 64, 64, 128, 3>,
        cudaFuncAttributeMaxDynamicSharedMemorySize, SMEM_BYTES(64, 64, 3));
    cudaFuncSetAttribute(depth_scores_k,
        cudaFuncAttributeMaxDynamicSharedMemorySize, (2 * 32 * 196 + 32 * 33) * 4);
    cudaFuncSetAttribute(depth_pinv_o_k,
        cudaFuncAttributeMaxDynamicSharedMemorySize, (6 * 1056 + 32 * DIM) * 4);

    const long TQ = 3 * DIM;          // qkv row stride (576)
    const long LQ = (long)NSP * TQ;   // depth fold row stride

    // ---- patch embed
    patchify_k<<<(SEQ * DIM + 255) / 256, 256>>>(volume, SRC);
    gemm(SRC, patch_w, X, patch_b, pos_emb, 0,
         SEQ, DIM, DIM, DIM, DIM, DIM, 0, 0, 0, 1, 1.f, 0);

    for (int L = 0; L < 4; L++) {
        // ================= depth attention (fused) ==========================
        rownorm_k<<<SEQ / 8, 256>>>(X, RS, gd, L, SEQ);
        gemm(X, qkv_depth + (long)L * DIM * TQ, QKV, 0, 0, RS,
             SEQ, 3 * DIM, DIM, DIM, TQ, TQ, 0, 0, 0, 1, 1.f, 0);
        reset2_k<<<1, 32>>>(RED);
        depth_scores_k<<<NSP, 256, (2 * 32 * 196 + 32 * 33) * 4>>>(QKV, A2, RED);
        depth_pinv_o_k<<<NSP, 256, (6 * 1056 + 32 * DIM) * 4>>>(A2, QKV, RED, O);
        gemm(O, outw_depth + (long)L * DIM * DIM, X, outb_depth + (long)L * DIM, X, 0,
             SEQ, DIM, DIM, DIM, DIM, DIM, 0, 0, 0, 1, 1.f, 0);

        // ================= spatial attention (b=32, n=1024, m=256) ==========
        rownorm_k<<<SEQ / 8, 256>>>(X, RS, gs, L, SEQ);
        gemm(X, qkv_spatial + (long)L * DIM * TQ, QKV, 0, 0, RS,
             SEQ, 3 * DIM, DIM, DIM, TQ, TQ, 0, 0, 0, 1, 1.f, 0);
        landmark_k<<<(32 * ML * DIM + 255) / 256, 256>>>(QKV, QL, KL);
        gemm(QKV, KL, A1, 0, 0, 0,
             NSP, ML, DIM, TQ, DIM, ML, LQ, (long)ML * DIM, (long)NSP * ML,
             32, SCALE_QK, 1);
        softmax_warp_k<8><<<(32 * NSP) / 8, 256>>>(A1, (long)32 * NSP);
        gemm(QL, KL, A2, 0, 0, 0,
             ML, ML, DIM, DIM, DIM, ML, (long)ML * DIM, (long)ML * DIM, (long)ML * ML,
             32, SCALE_QK, 1);
        softmax_warp_k<8><<<(32 * ML) / 8, 256>>>(A2, (long)32 * ML);
        gemm(QL, QKV + DIM, A3, 0, 0, 0,
             ML, NSP, DIM, DIM, TQ, NSP, (long)ML * DIM, LQ, (long)ML * NSP,
             32, SCALE_QK, 1);
        softmax_warp_k<32><<<(32 * ML) / 8, 256>>>(A3, (long)32 * ML);
        run_pinv(A2, ML, 32, Z, Z2, T1, T2, T3, RED);
        gemm(A3, QKV + 2 * DIM, A3V, 0, 0, 0,
             ML, DIM, NSP, NSP, TQ, DIM, (long)ML * NSP, LQ, (long)ML * DIM,
             32, 1.f, 0);
        gemm(Z, A3V, ZV, 0, 0, 0,
             ML, DIM, ML, ML, DIM, DIM, (long)ML * ML, (long)ML * DIM, (long)ML * DIM,
             32, 1.f, 0);
        gemm(A1, ZV, O, 0, 0, 0,
             NSP, DIM, ML, ML, DIM, DIM, (long)NSP * ML, (long)ML * DIM, (long)NSP * DIM,
             32, 1.f, 0);
        gemm(O, outw_spatial + (long)L * DIM * DIM, X, outb_spatial + (long)L * DIM, X, 0,
             SEQ, DIM, DIM, DIM, DIM, DIM, 0, 0, 0, 1, 1.f, 0);

        // ================= GEGLU FF (fused) =================================
        rownorm_k<<<SEQ / 8, 256>>>(X, RS, gf, L, SEQ);
        permw1_k<<<(DIM * 8 * DIM + 255) / 256, 256>>>(
            ff_w1 + (long)L * DIM * 8 * DIM, ff_b1 + (long)L * 8 * DIM, W1P, B1P);
        gemm_full(X, W1P, GG, 0, B1P, 0, RS,
                  SEQ, 8 * DIM, DIM, DIM, 8 * DIM, 4 * DIM, 0, 0, 0,
                  1, 1.f, 0, 0, 0.f, 0.f, 1);
        gemm(GG, ff_w2 + (long)L * 4 * DIM * DIM, X, ff_b2 + (long)L * DIM, X, 0,
             SEQ, DIM, 4 * DIM, 4 * DIM, DIM, DIM, 0, 0, 0, 1, 1.f, 0);
    }

    // ---- final scale_norm -> output
    scale_norm_k<<<SEQ / 8, 256>>>(X, (float*)d_out, g_fin, 0, SEQ);
}

// round 17
// speedup vs baseline: 1.0283x; 1.0283x over previous
#include <cuda_runtime.h>
#include <math.h>
#include <mma.h>

using namespace nvcuda;

// ---------------------------------------------------------------------------
// DepthFormer (Nystrom attention) — round 17 (third submit of the R15 kernel
// after two infra failures): fast-path epilogue ONLY on the small-tile
// template (big path codegen identical to R13 best); warp softmax.
// seq = 32768, dim = 192, 4 layers.
// ---------------------------------------------------------------------------

#define DIM 192
#define SEQ 32768
#define FD 32          // depth (f)
#define NSP 1024       // spatial positions per depth slice (n)
#define ML 256         // spatial landmarks
#define SCALE_QK 0.07216878364870322f   // 192^-0.5

// ------------------------------ scratch ------------------------------------
__device__ float g_x  [SEQ * DIM];
__device__ float g_src[SEQ * DIM];
__device__ float g_qkv[SEQ * 3 * DIM];
__device__ float g_ql [32 * ML * DIM];
__device__ float g_kl [32 * ML * DIM];
__device__ float g_a1 [32 * NSP * ML];
__device__ float g_a2 [32 * ML * ML];
__device__ float g_a3 [32 * ML * NSP];
__device__ float g_zb [32 * ML * ML];
__device__ float g_z2 [32 * ML * ML];
__device__ float g_t1 [32 * ML * ML];
__device__ float g_t2 [32 * ML * ML];
__device__ float g_t3 [32 * ML * ML];
__device__ float g_a3v[32 * ML * DIM];
__device__ float g_zv [32 * ML * DIM];
__device__ float g_o  [SEQ * DIM];
__device__ float g_gg [SEQ * 4 * DIM];
__device__ float g_w1p[DIM * 8 * DIM];
__device__ float g_b1p[8 * DIM];
__device__ float g_rs [SEQ];
__device__ float g_red[2];

// ------------------------------ GEMM ---------------------------------------
struct GemmP {
    const float* A; const float* B; float* C; float* C2;
    const float* bias; const float* resid; const float* rowS;
    int K, diagMode, geglu;
    long lda, ldb, ldc, sA, sB, sC;
    float alpha, diag1, diag2;
};

#define CP16(dst_u32, src) \
    asm volatile("cp.async.cg.shared.global [%0], [%1], 16;" :: "r"(dst_u32), "l"(src))
#define CP_COMMIT() asm volatile("cp.async.commit_group;")

template<int N> __device__ __forceinline__ void cp_wait() {
    asm volatile("cp.async.wait_group %0;" :: "n"(N));
}

#define STG_OF(BM, BN) ((BM) * 36 + ((32 * ((BN) + 4) > (BN) * 36) ? 32 * ((BN) + 4) : (BN) * 36))
#define SMEM_BYTES(BM, BN, NST) ((NST) * STG_OF(BM, BN) * 4)

// TF32 wmma GEMM, cp.async NST-stage pipeline, 1 barrier per K-iter.
// M % BM == 0, N % BN == 0, K % 32 == 0, K >= 32*(NST-1), rows 16B aligned.
// FASTEP: compile in the direct fragment-store epilogue (small path only).
template<int TRANSB, int BM, int BN, int NTHR, int NST, int FASTEP>
__global__ void __launch_bounds__(NTHR) tgemm(GemmP p) {
    constexpr int BK = 32;
    constexpr int LDA = 36;
    constexpr int LDBN = BN + 4;
    constexpr int LDBT = 36;
    constexpr int LDC = BN + 4;
    constexpr int STG = STG_OF(BM, BN);
    constexpr int NCA = BM * 8 / NTHR;
    constexpr int NCB = BN * 8 / NTHR;
    constexpr int WNB = BN / 32;
    extern __shared__ float smem[];

    int bz = blockIdx.z;
    const float* A = p.A + (long)bz * p.sA;
    const float* B = p.B + (long)bz * p.sB;
    float*       C = p.C + (long)bz * p.sC;
    int m0 = blockIdx.y * BM, n0 = blockIdx.x * BN;
    int tid = threadIdx.x;
    int warp = tid >> 5;
    int wm = (warp / WNB) * 32;
    int wn = (warp % WNB) * 32;

    const float* aG[NCA]; int aS[NCA];
    #pragma unroll
    for (int i = 0; i < NCA; i++) {
        int idx = tid + i * NTHR;
        aG[i] = A + (long)(m0 + (idx >> 3)) * p.lda + ((idx & 7) << 2);
        aS[i] = (idx >> 3) * LDA + ((idx & 7) << 2);
    }
    const float* bG[NCB]; int bS[NCB];
    if (!TRANSB) {
        #pragma unroll
        for (int i = 0; i < NCB; i++) {
            int idx = tid + i * NTHR;
            bG[i] = B + (long)(idx / (BN / 4)) * p.ldb + n0 + ((idx % (BN / 4)) << 2);
            bS[i] = BM * LDA + (idx / (BN / 4)) * LDBN + ((idx % (BN / 4)) << 2);
        }
    } else {
        #pragma unroll
        for (int i = 0; i < NCB; i++) {
            int idx = tid + i * NTHR;
            bG[i] = B + (long)(n0 + (idx >> 3)) * p.ldb + ((idx & 7) << 2);
            bS[i] = BM * LDA + (idx >> 3) * LDBT + ((idx & 7) << 2);
        }
    }
    unsigned smem_u32 = (unsigned)__cvta_generic_to_shared(smem);
    long bstep = TRANSB ? 32 : 32 * p.ldb;

    wmma::fragment<wmma::accumulator, 16, 16, 8, float> cfr[2][2];
    #pragma unroll
    for (int i = 0; i < 2; i++)
        #pragma unroll
        for (int j = 0; j < 2; j++) wmma::fill_fragment(cfr[i][j], 0.f);

    int NSTEP = p.K >> 5;
    #pragma unroll
    for (int s = 0; s < NST - 1; s++) {
        unsigned base = smem_u32 + s * (STG * 4);
        #pragma unroll
        for (int i = 0; i < NCA; i++) CP16(base + aS[i] * 4, aG[i] + s * 32);
        #pragma unroll
        for (int i = 0; i < NCB; i++) CP16(base + bS[i] * 4, bG[i] + s * bstep);
        CP_COMMIT();
    }

    int cbuf = 0;
    int pbuf = NST - 1;
    for (int s = 0; s < NSTEP; s++) {
        cp_wait<NST - 2>();
        __syncthreads();
        int pf = s + NST - 1;
        if (pf < NSTEP) {
            unsigned base = smem_u32 + pbuf * (STG * 4);
            #pragma unroll
            for (int i = 0; i < NCA; i++) CP16(base + aS[i] * 4, aG[i] + (long)pf * 32);
            #pragma unroll
            for (int i = 0; i < NCB; i++) CP16(base + bS[i] * 4, bG[i] + (long)pf * bstep);
        }
        CP_COMMIT();

        float* As = smem + cbuf * STG;
        float* Bs = As + BM * LDA;
        #pragma unroll
        for (int kk = 0; kk < BK; kk += 8) {
            wmma::fragment<wmma::matrix_a, 16, 16, 8, wmma::precision::tf32, wmma::row_major> a[2];
            #pragma unroll
            for (int i = 0; i < 2; i++)
                wmma::load_matrix_sync(a[i], &As[(wm + i * 16) * LDA + kk], LDA);
            if (!TRANSB) {
                wmma::fragment<wmma::matrix_b, 16, 16, 8, wmma::precision::tf32, wmma::row_major> b[2];
                #pragma unroll
                for (int j = 0; j < 2; j++)
                    wmma::load_matrix_sync(b[j], &Bs[kk * LDBN + wn + j * 16], LDBN);
                #pragma unroll
                for (int i = 0; i < 2; i++)
                    #pragma unroll
                    for (int j = 0; j < 2; j++)
                        wmma::mma_sync(cfr[i][j], a[i], b[j], cfr[i][j]);
            } else {
                wmma::fragment<wmma::matrix_b, 16, 16, 8, wmma::precision::tf32, wmma::col_major> b[2];
                #pragma unroll
                for (int j = 0; j < 2; j++)
                    wmma::load_matrix_sync(b[j], &Bs[(wn + j * 16) * LDBT + kk], LDBT);
                #pragma unroll
                for (int i = 0; i < 2; i++)
                    #pragma unroll
                    for (int j = 0; j < 2; j++)
                        wmma::mma_sync(cfr[i][j], a[i], b[j], cfr[i][j]);
            }
        }
        cbuf = (cbuf + 1 == NST) ? 0 : cbuf + 1;
        pbuf = (pbuf + 1 == NST) ? 0 : pbuf + 1;
    }
    cp_wait<0>();

    if constexpr (FASTEP) {
        // direct fragment store: no smem, no barriers. Valid when no
        // row/col elementwise data and tile doesn't touch diag of a
        // diag-style output.
        bool needDiag = (p.diagMode || p.C2) &&
                        (n0 < m0 + BM) && (m0 < n0 + BN);
        if (!p.geglu && !p.bias && !p.resid && !p.rowS && !needDiag) {
            float s1 = p.diagMode ? -p.alpha : p.alpha;
            #pragma unroll
            for (int i = 0; i < 2; i++)
                #pragma unroll
                for (int j = 0; j < 2; j++) {
                    #pragma unroll
                    for (int e = 0; e < cfr[i][j].num_elements; e++)
                        cfr[i][j].x[e] *= s1;
                    wmma::store_matrix_sync(
                        C + (long)(m0 + wm + i * 16) * p.ldc + n0 + wn + j * 16,
                        cfr[i][j], p.ldc, wmma::mem_row_major);
                }
            if (p.C2) {   // off-diagonal tile of C2 = diag2*I - v  ->  -v
                float* C2p = p.C2 + (long)bz * p.sC;
                #pragma unroll
                for (int i = 0; i < 2; i++)
                    #pragma unroll
                    for (int j = 0; j < 2; j++) {
                        #pragma unroll
                        for (int e = 0; e < cfr[i][j].num_elements; e++)
                            cfr[i][j].x[e] = -cfr[i][j].x[e];
                        wmma::store_matrix_sync(
                            C2p + (long)(m0 + wm + i * 16) * p.ldc + n0 + wn + j * 16,
                            cfr[i][j], p.ldc, wmma::mem_row_major);
                    }
            }
            return;
        }
    }

    __syncthreads();
    float* Cs = smem;
    #pragma unroll
    for (int i = 0; i < 2; i++)
        #pragma unroll
        for (int j = 0; j < 2; j++)
            wmma::store_matrix_sync(&Cs[(wm + i * 16) * LDC + wn + j * 16],
                                    cfr[i][j], LDC, wmma::mem_row_major);
    __syncthreads();

    if (p.geglu) {
        for (int i = tid; i < BM * (BN / 2); i += NTHR) {
            int r = i / (BN / 2), q = i % (BN / 2);
            int m = m0 + r;
            float sc = p.alpha * (p.rowS ? p.rowS[m] : 1.f);
            float av = Cs[r * LDC + 2 * q]     * sc + p.bias[n0 + 2 * q];
            float gv = Cs[r * LDC + 2 * q + 1] * sc + p.bias[n0 + 2 * q + 1];
            float ge = 0.5f * gv * (1.f + erff(gv * 0.70710678118654752f));
            C[(long)m * p.ldc + (n0 >> 1) + q] = av * ge;
        }
        return;
    }

    for (int i = tid; i < BM * BN; i += NTHR) {
        int r = i / BN, cn = i % BN;
        int m = m0 + r, n = n0 + cn;
        float v = Cs[r * LDC + cn] * p.alpha;
        if (p.rowS) v *= p.rowS[m];
        long co = (long)m * p.ldc + n;
        float out;
        if (p.diagMode) {
            out = (m == n ? p.diag1 : 0.f) - v;
        } else {
            out = v;
            if (p.bias)  out += p.bias[n];
            if (p.resid) out += p.resid[(long)bz * p.sC + co];
        }
        C[co] = out;
        if (p.C2) p.C2[(long)bz * p.sC + co] = (m == n ? p.diag2 : 0.f) - v;
    }
}

static void gemm_full(const float* A, const float* B, float* C, float* C2,
                      const float* bias, const float* resid, const float* rowS,
                      int M, int N, int K,
                      long lda, long ldb, long ldc,
                      long sA, long sB, long sC,
                      int batch, float alpha, int transB,
                      int diagMode, float diag1, float diag2, int geglu) {
    GemmP p{A, B, C, C2, bias, resid, rowS, K, diagMode, geglu,
            lda, ldb, ldc, sA, sB, sC, alpha, diag1, diag2};
    if (M <= 256) {
        dim3 grid(N / 64, M / 64, batch);
        if (transB) tgemm<1, 64, 64, 128, 3, 1><<<grid, 128, SMEM_BYTES(64, 64, 3)>>>(p);
        else        tgemm<0, 64, 64, 128, 3, 1><<<grid, 128, SMEM_BYTES(64, 64, 3)>>>(p);
    } else {
        dim3 grid(N / 64, M / 128, batch);
        if (transB) tgemm<1, 128, 64, 256, 4, 0><<<grid, 256, SMEM_BYTES(128, 64, 4)>>>(p);
        else        tgemm<0, 128, 64, 256, 4, 0><<<grid, 256, SMEM_BYTES(128, 64, 4)>>>(p);
    }
}

static void gemm(const float* A, const float* B, float* C,
                 const float* bias, const float* resid, const float* rowS,
                 int M, int N, int K,
                 long lda, long ldb, long ldc,
                 long sA, long sB, long sC,
                 int batch, float alpha, int transB) {
    gemm_full(A, B, C, 0, bias, resid, rowS, M, N, K, lda, ldb, ldc, sA, sB, sC,
              batch, alpha, transB, 0, 0.f, 0.f, 0);
}

// --------------------------- elementwise / reductions -----------------------
__device__ __forceinline__ float warp_red_sum(float v) {
    #pragma unroll
    for (int o = 16; o > 0; o >>= 1) v += __shfl_xor_sync(0xffffffffu, v, o);
    return v;
}
__device__ __forceinline__ float warp_red_max(float v) {
    #pragma unroll
    for (int o = 16; o > 0; o >>= 1) v = fmaxf(v, __shfl_xor_sync(0xffffffffu, v, o));
    return v;
}

__global__ void rownorm_k(const float* __restrict__ x, float* __restrict__ s,
                          const float* __restrict__ g, int gidx, int rows) {
    int warp = (blockIdx.x * blockDim.x + threadIdx.x) >> 5;
    int lane = threadIdx.x & 31;
    if (warp >= rows) return;
    const float* xr = x + (long)warp * DIM;
    float acc = 0.f;
    #pragma unroll
    for (int i = 0; i < 6; i++) { float v = xr[lane + i * 32]; acc += v * v; }
    acc = warp_red_sum(acc);
    if (lane == 0) s[warp] = g[gidx] / fmaxf(sqrtf(acc), 1e-5f);
}

__global__ void scale_norm_k(const float* __restrict__ x, float* __restrict__ y,
                             const float* __restrict__ g, int gidx, int rows) {
    int warp = (blockIdx.x * blockDim.x + threadIdx.x) >> 5;
    int lane = threadIdx.x & 31;
    if (warp >= rows) return;
    const float* xr = x + (long)warp * DIM;
    float v[6], s = 0.f;
    #pragma unroll
    for (int i = 0; i < 6; i++) { v[i] = xr[lane + i * 32]; s += v[i] * v[i]; }
    s = warp_red_sum(s);
    float scale = g[gidx] / fmaxf(sqrtf(s), 1e-5f);
    float* yr = y + (long)warp * DIM;
    #pragma unroll
    for (int i = 0; i < 6; i++) yr[lane + i * 32] = v[i] * scale;
}

// warp-per-row softmax; EL = elements per lane (len = 32*EL); 8 rows/block.
template<int EL>
__global__ void __launch_bounds__(256) softmax_warp_k(float* __restrict__ x, long rows) {
    long row = (long)blockIdx.x * 8 + (threadIdx.x >> 5);
    if (row >= rows) return;
    int lane = threadIdx.x & 31;
    float* xr = x + row * (32 * EL);
    float v[EL];
    float mx = -3.0e38f;
    #pragma unroll
    for (int i = 0; i < EL; i++) { v[i] = xr[lane + (i << 5)]; mx = fmaxf(mx, v[i]); }
    mx = warp_red_max(mx);
    float s = 0.f;
    #pragma unroll
    for (int i = 0; i < EL; i++) { v[i] = expf(v[i] - mx); s += v[i]; }
    s = warp_red_sum(s);
    float inv = 1.f / s;
    #pragma unroll
    for (int i = 0; i < EL; i++) xr[lane + (i << 5)] = v[i] * inv;
}

__global__ void landmark_k(const float* __restrict__ qkv,
                           float* __restrict__ ql, float* __restrict__ kl) {
    int idx = blockIdx.x * blockDim.x + threadIdx.x;
    if (idx >= 32 * ML * DIM) return;
    int d = idx % DIM;
    int j = (idx / DIM) % ML;
    int b = idx / (DIM * ML);
    long base = ((long)b * NSP + j * 4) * (3 * DIM);
    float q = 0.f, k = 0.f;
    #pragma unroll
    for (int i = 0; i < 4; i++) {
        q += qkv[base + (long)i * (3 * DIM) + d];
        k += qkv[base + (long)i * (3 * DIM) + DIM + d];
    }
    ql[idx] = q * 0.25f;
    kl[idx] = k * 0.25f;
}

// red[0] = 1 (softmax rows sum to 1); red[1] cleared for colsum max
__global__ void reset2_k(float* r) {
    if (threadIdx.x == 0) r[0] = 1.0f;
    if (threadIdx.x == 1) r[1] = 0.f;
}

__global__ void colsum_max_k(const float* __restrict__ x, int m, float* red) {
    long col = blockIdx.x;
    int b = (int)(col / m), j = (int)(col % m);
    const float* xb = x + (long)b * m * m;
    __shared__ float sh[32];
    int tid = threadIdx.x, lane = tid & 31, w = tid >> 5, nw = blockDim.x >> 5;
    float s = 0.f;
    for (int i = tid; i < m; i += blockDim.x) s += fabsf(xb[(long)i * m + j]);
    s = warp_red_sum(s);
    if (lane == 0) sh[w] = s;
    __syncthreads();
    if (tid == 0) {
        float t = 0.f;
        for (int i = 0; i < nw; i++) t += sh[i];
        atomicMax((int*)(red + 1), __float_as_int(t));
    }
}

__global__ void zinit_k(const float* __restrict__ x, float* __restrict__ z,
                        const float* __restrict__ red, int m, long total) {
    long idx = (long)blockIdx.x * blockDim.x + threadIdx.x;
    if (idx >= total) return;
    long mm = (long)m * m;
    long b = idx / mm;
    int ij = (int)(idx % mm);
    int r = ij / m, c = ij % m;
    float inv = 1.f / (red[0] * red[1]);
    z[idx] = x[b * mm + (long)c * m + r] * inv;
}

__global__ void permw1_k(const float* __restrict__ w1, const float* __restrict__ b1,
                         float* __restrict__ w1p, float* __restrict__ b1p) {
    int idx = blockIdx.x * blockDim.x + threadIdx.x;
    if (idx < 8 * DIM) {
        int j = idx >> 1;
        b1p[idx] = (idx & 1) ? b1[j + 4 * DIM] : b1[j];
    }
    if (idx >= DIM * 8 * DIM) return;
    int n = idx % (8 * DIM), k = idx / (8 * DIM);
    int j = n >> 1;
    int src = (n & 1) ? j + 4 * DIM : j;
    w1p[idx] = w1[k * (8 * DIM) + src];
}

__global__ void patchify_k(const float* __restrict__ vol, float* __restrict__ out) {
    long idx = (long)blockIdx.x * blockDim.x + threadIdx.x;
    if (idx >= (long)SEQ * DIM) return;
    int j = (int)(idx % DIM);
    long t = idx / DIM;
    int d = (int)(t / NSP);
    int rem = (int)(t % NSP);
    int h = rem / 32, w = rem % 32;
    int p1 = j / 24;
    int p2 = (j / 3) & 7;
    int c = j % 3;
    long off = ((long)c * 32 + d) * 65536 + (long)(h * 8 + p1) * 256 + (w * 8 + p2);
    out[idx] = vol[off];
}

// --------------------- fused depth attention (f=32 per spatial pos) ---------
__global__ void __launch_bounds__(256) depth_scores_k(
        const float* __restrict__ qkv, float* __restrict__ a2out,
        float* __restrict__ red) {
    extern __shared__ float sm[];
    float* q = sm;
    float* k = sm + 32 * 196;
    float* S = k + 32 * 196;
    int nb = blockIdx.x, t = threadIdx.x;

    for (int idx = t; idx < 32 * DIM; idx += 256) {
        int f = idx / DIM, d = idx % DIM;
        long base = ((long)f * NSP + nb) * (3 * DIM);
        q[f * 196 + d] = qkv[base + d];
        k[f * 196 + d] = qkv[base + DIM + d];
    }
    __syncthreads();

    int i = t >> 3, j0 = t & 7;
    float s[4];
    #pragma unroll
    for (int jj = 0; jj < 4; jj++) {
        int j = j0 + 8 * jj;
        float acc = 0.f;
        for (int d = 0; d < DIM; d++) acc += q[i * 196 + d] * k[j * 196 + d];
        s[jj] = acc * SCALE_QK;
    }
    float mx = fmaxf(fmaxf(s[0], s[1]), fmaxf(s[2], s[3]));
    #pragma unroll
    for (int o = 4; o > 0; o >>= 1) mx = fmaxf(mx, __shfl_xor_sync(0xffffffffu, mx, o));
    float sum = 0.f;
    #pragma unroll
    for (int jj = 0; jj < 4; jj++) { s[jj] = expf(s[jj] - mx); sum += s[jj]; }
    #pragma unroll
    for (int o = 4; o > 0; o >>= 1) sum += __shfl_xor_sync(0xffffffffu, sum, o);
    float inv = 1.f / sum;
    #pragma unroll
    for (int jj = 0; jj < 4; jj++) {
        int j = j0 + 8 * jj;
        float v = s[jj] * inv;
        S[i * 33 + j] = v;
        a2out[(long)nb * 1024 + i * 32 + j] = v;
    }
    __syncthreads();
    if (t < 32) {               // column sums only (rowsum == 1 by softmax)
        float cs = 0.f;
        for (int r = 0; r < 32; r++) cs += S[r * 33 + t];
        cs = warp_red_max(cs);
        if (t == 0) atomicMax((int*)(red + 1), __float_as_int(cs));
    }
}

__device__ __forceinline__ void mm32(const float* A, const float* B, float* C,
                                     int t, int diag, float cst) {
    int i = t >> 3, j0 = t & 7;
    float acc[4] = {0.f, 0.f, 0.f, 0.f};
    #pragma unroll
    for (int kk = 0; kk < 32; kk++) {
        float a = A[i * 33 + kk];
        #pragma unroll
        for (int jj = 0; jj < 4; jj++) acc[jj] += a * B[kk * 33 + j0 + 8 * jj];
    }
    #pragma unroll
    for (int jj = 0; jj < 4; jj++) {
        int j = j0 + 8 * jj;
        C[i * 33 + j] = diag ? ((i == j ? cst : 0.f) - acc[jj]) : cst * acc[jj];
    }
}
__device__ __forceinline__ void mm32dual(const float* A, const float* B,
                                         float* C1, float* C2, int t, float cst) {
    int i = t >> 3, j0 = t & 7;
    float acc[4] = {0.f, 0.f, 0.f, 0.f};
    #pragma unroll
    for (int kk = 0; kk < 32; kk++) {
        float a = A[i * 33 + kk];
        #pragma unroll
        for (int jj = 0; jj < 4; jj++) acc[jj] += a * B[kk * 33 + j0 + 8 * jj];
    }
    #pragma unroll
    for (int jj = 0; jj < 4; jj++) {
        int j = j0 + 8 * jj;
        C1[i * 33 + j] = acc[jj];
        C2[i * 33 + j] = (i == j ? cst : 0.f) - acc[jj];
    }
}

__global__ void __launch_bounds__(256) depth_pinv_o_k(
        const float* __restrict__ a2in, const float* __restrict__ qkv,
        const float* __restrict__ red, float* __restrict__ Oout) {
    extern __shared__ float sm[];
    float* A  = sm;
    float* Z0 = A  + 1056;
    float* Z1 = Z0 + 1056;
    float* T1 = Z1 + 1056;
    float* T2 = T1 + 1056;
    float* T3 = T2 + 1056;
    float* V  = T3 + 1056;
    int nb = blockIdx.x, t = threadIdx.x;

    for (int idx = t; idx < 1024; idx += 256)
        A[(idx >> 5) * 33 + (idx & 31)] = a2in[(long)nb * 1024 + idx];
    for (int idx = t; idx < 32 * DIM; idx += 256) {
        int f = idx / DIM, d = idx % DIM;
        V[f * DIM + d] = qkv[((long)f * NSP + nb) * (3 * DIM) + 2 * DIM + d];
    }
    float inv = 1.f / (red[0] * red[1]);
    __syncthreads();
    for (int idx = t; idx < 1024; idx += 256) {
        int r = idx >> 5, c = idx & 31;
        Z0[r * 33 + c] = A[c * 33 + r] * inv;
    }
    __syncthreads();

    float* P = Z0; float* Pn = Z1;
    #pragma unroll 1
    for (int it = 0; it < 6; it++) {
        mm32dual(A, P, T1, T2, t, 7.f);   __syncthreads();
        mm32(T1, T2, T3, t, 1, 15.f);     __syncthreads();
        mm32(T1, T3, T2, t, 1, 13.f);     __syncthreads();
        mm32(P,  T2, Pn, t, 0, 0.25f);    __syncthreads();
        float* tmp = P; P = Pn; Pn = tmp;
    }
    mm32(A, P, T1, t, 0, 1.f);  __syncthreads();
    mm32(T1, A, T2, t, 0, 1.f); __syncthreads();

    int i = t >> 3, d0 = t & 7;
    #pragma unroll 4
    for (int m = 0; m < 24; m++) {
        int d = d0 + 8 * m;
        float acc = 0.f;
        #pragma unroll
        for (int kk = 0; kk < 32; kk++) acc += T2[i * 33 + kk] * V[kk * DIM + d];
        Oout[((long)i * NSP + nb) * DIM + d] = acc;
    }
}

// ------------------------------ pinv (spatial, m=256) -----------------------
static void run_pinv(float* X, int m, int batch,
                     float* Z, float* Z2, float* T1, float* T2, float* T3,
                     float* red) {
    long mm = (long)m * m;
    long total = mm * batch;
    reset2_k<<<1, 32>>>(red);
    colsum_max_k<<<batch * m, 128>>>(X, m, red);
    zinit_k<<<(int)((total + 255) / 256), 256>>>(X, Z, red, m, total);
    float* zc = Z; float* zn = Z2;
    for (int it = 0; it < 6; it++) {
        gemm_full(X, zc, T1, T2, 0, 0, 0, m, m, m, m, m, m, mm, mm, mm,
                  batch, 1.f, 0, 0, 0.f, 7.f, 0);
        gemm_full(T1, T2, T3, 0, 0, 0, 0, m, m, m, m, m, m, mm, mm, mm,
                  batch, 1.f, 0, 1, 15.f, 0.f, 0);
        gemm_full(T1, T3, T2, 0, 0, 0, 0, m, m, m, m, m, m, mm, mm, mm,
                  batch, 1.f, 0, 1, 13.f, 0.f, 0);
        gemm(zc, T2, zn, 0, 0, 0, m, m, m, m, m, m, mm, mm, mm, batch, 0.25f, 0);
        float* tmp = zc; zc = zn; zn = tmp;
    }
}

// ------------------------------ launch -------------------------------------
template <typename T>
static float* symptr(T& sym) { void* p = 0; cudaGetSymbolAddress(&p, sym); return (float*)p; }

extern "C" void kernel_launch(void* const* d_in, const int* in_sizes, int n_in,
                              void* d_out, int out_size) {
    const float* volume      = (const float*)d_in[0];
    const float* patch_w     = (const float*)d_in[1];
    const float* patch_b     = (const float*)d_in[2];
    const float* pos_emb     = (const float*)d_in[3];
    const float* gd          = (const float*)d_in[4];
    const float* qkv_depth   = (const float*)d_in[5];
    const float* outw_depth  = (const float*)d_in[6];
    const float* outb_depth  = (const float*)d_in[7];
    const float* gs          = (const float*)d_in[8];
    const float* qkv_spatial = (const float*)d_in[9];
    const float* outw_spatial= (const float*)d_in[10];
    const float* outb_spatial= (const float*)d_in[11];
    const float* gf          = (const float*)d_in[12];
    const float* ff_w1       = (const float*)d_in[13];
    const float* ff_b1       = (const float*)d_in[14];
    const float* ff_w2       = (const float*)d_in[15];
    const float* ff_b2       = (const float*)d_in[16];
    const float* g_fin       = (const float*)d_in[17];

    float* X   = symptr(g_x);
    float* SRC = symptr(g_src);
    float* QKV = symptr(g_qkv);
    float* QL  = symptr(g_ql);
    float* KL  = symptr(g_kl);
    float* A1  = symptr(g_a1);
    float* A2  = symptr(g_a2);
    float* A3  = symptr(g_a3);
    float* Z   = symptr(g_zb);
    float* Z2  = symptr(g_z2);
    float* T1  = symptr(g_t1);
    float* T2  = symptr(g_t2);
    float* T3  = symptr(g_t3);
    float* A3V = symptr(g_a3v);
    float* ZV  = symptr(g_zv);
    float* O   = symptr(g_o);
    float* GG  = symptr(g_gg);
    float* W1P = symptr(g_w1p);
    float* B1P = symptr(g_b1p);
    float* RS  = symptr(g_rs);
    float* RED = symptr(g_red);

    cudaFuncSetAttribute((void*)tgemm<0, 128, 64, 256, 4, 0>,
        cudaFuncAttributeMaxDynamicSharedMemorySize, SMEM_BYTES(128, 64, 4));
    cudaFuncSetAttribute((void*)tgemm<1, 128, 64, 256, 4, 0>,
        cudaFuncAttributeMaxDynamicSharedMemorySize, SMEM_BYTES(128, 64, 4));
    cudaFuncSetAttribute((void*)tgemm<0, 64, 64, 128, 3, 1>,
        cudaFuncAttributeMaxDynamicSharedMemorySize, SMEM_BYTES(64, 64, 3));
    cudaFuncSetAttribute((void*)tgemm<1, 64, 64, 128, 3, 1>,
        cudaFuncAttributeMaxDynamicSharedMemorySize, SMEM_BYTES(64, 64, 3));
    cudaFuncSetAttribute(depth_scores_k,
        cudaFuncAttributeMaxDynamicSharedMemorySize, (2 * 32 * 196 + 32 * 33) * 4);
    cudaFuncSetAttribute(depth_pinv_o_k,
        cudaFuncAttributeMaxDynamicSharedMemorySize, (6 * 1056 + 32 * DIM) * 4);

    const long TQ = 3 * DIM;          // qkv row stride (576)
    const long LQ = (long)NSP * TQ;   // depth fold row stride

    // ---- patch embed
    patchify_k<<<(SEQ * DIM + 255) / 256, 256>>>(volume, SRC);
    gemm(SRC, patch_w, X, patch_b, pos_emb, 0,
         SEQ, DIM, DIM, DIM, DIM, DIM, 0, 0, 0, 1, 1.f, 0);

    for (int L = 0; L < 4; L++) {
        // ================= depth attention (fused) ==========================
        rownorm_k<<<SEQ / 8, 256>>>(X, RS, gd, L, SEQ);
        gemm(X, qkv_depth + (long)L * DIM * TQ, QKV, 0, 0, RS,
             SEQ, 3 * DIM, DIM, DIM, TQ, TQ, 0, 0, 0, 1, 1.f, 0);
        reset2_k<<<1, 32>>>(RED);
        depth_scores_k<<<NSP, 256, (2 * 32 * 196 + 32 * 33) * 4>>>(QKV, A2, RED);
        depth_pinv_o_k<<<NSP, 256, (6 * 1056 + 32 * DIM) * 4>>>(A2, QKV, RED, O);
        gemm(O, outw_depth + (long)L * DIM * DIM, X, outb_depth + (long)L * DIM, X, 0,
             SEQ, DIM, DIM, DIM, DIM, DIM, 0, 0, 0, 1, 1.f, 0);

        // ================= spatial attention (b=32, n=1024, m=256) ==========
        rownorm_k<<<SEQ / 8, 256>>>(X, RS, gs, L, SEQ);
        gemm(X, qkv_spatial + (long)L * DIM * TQ, QKV, 0, 0, RS,
             SEQ, 3 * DIM, DIM, DIM, TQ, TQ, 0, 0, 0, 1, 1.f, 0);
        landmark_k<<<(32 * ML * DIM + 255) / 256, 256>>>(QKV, QL, KL);
        gemm(QKV, KL, A1, 0, 0, 0,
             NSP, ML, DIM, TQ, DIM, ML, LQ, (long)ML * DIM, (long)NSP * ML,
             32, SCALE_QK, 1);
        softmax_warp_k<8><<<(32 * NSP) / 8, 256>>>(A1, (long)32 * NSP);
        gemm(QL, KL, A2, 0, 0, 0,
             ML, ML, DIM, DIM, DIM, ML, (long)ML * DIM, (long)ML * DIM, (long)ML * ML,
             32, SCALE_QK, 1);
        softmax_warp_k<8><<<(32 * ML) / 8, 256>>>(A2, (long)32 * ML);
        gemm(QL, QKV + DIM, A3, 0, 0, 0,
             ML, NSP, DIM, DIM, TQ, NSP, (long)ML * DIM, LQ, (long)ML * NSP,
             32, SCALE_QK, 1);
        softmax_warp_k<32><<<(32 * ML) / 8, 256>>>(A3, (long)32 * ML);
        run_pinv(A2, ML, 32, Z, Z2, T1, T2, T3, RED);
        gemm(A3, QKV + 2 * DIM, A3V, 0, 0, 0,
             ML, DIM, NSP, NSP, TQ, DIM, (long)ML * NSP, LQ, (long)ML * DIM,
             32, 1.f, 0);
        gemm(Z, A3V, ZV, 0, 0, 0,
             ML, DIM, ML, ML, DIM, DIM, (long)ML * ML, (long)ML * DIM, (long)ML * DIM,
             32, 1.f, 0);
        gemm(A1, ZV, O, 0, 0, 0,
             NSP, DIM, ML, ML, DIM, DIM, (long)NSP * ML, (long)ML * DIM, (long)NSP * DIM,
             32, 1.f, 0);
        gemm(O, outw_spatial + (long)L * DIM * DIM, X, outb_spatial + (long)L * DIM, X, 0,
             SEQ, DIM, DIM, DIM, DIM, DIM, 0, 0, 0, 1, 1.f, 0);

        // ================= GEGLU FF (fused) =================================
        rownorm_k<<<SEQ / 8, 256>>>(X, RS, gf, L, SEQ);
        permw1_k<<<(DIM * 8 * DIM + 255) / 256, 256>>>(
            ff_w1 + (long)L * DIM * 8 * DIM, ff_b1 + (long)L * 8 * DIM, W1P, B1P);
        gemm_full(X, W1P, GG, 0, B1P, 0, RS,
                  SEQ, 8 * DIM, DIM, DIM, 8 * DIM, 4 * DIM, 0, 0, 0,
                  1, 1.f, 0, 0, 0.f, 0.f, 1);
        gemm(GG, ff_w2 + (long)L * 4 * DIM * DIM, X, ff_b2 + (long)L * DIM, X, 0,
             SEQ, DIM, 4 * DIM, 4 * DIM, DIM, DIM, 0, 0, 0, 1, 1.f, 0);
    }

    // ---- final scale_norm -> output
    scale_norm_k<<<SEQ / 8, 256>>>(X, (float*)d_out, g_fin, 0, SEQ);
}